// round 4
// baseline (speedup 1.0000x reference)
#include <cuda_runtime.h>
#include <math.h>

// Problem constants
#define NB    16
#define NC    512
#define NPIX  1024          // H*W
#define NHEADS 4
#define HD    128
#define NGROUPS 32

// Scratch (device globals; allocation-free contract)
__device__ float g_h   [NB * NC * NPIX];                 // 32 MB  normalized input
__device__ float g_qkv [NB * 3 * NC * NPIX];             // 96 MB  qkv activations
__device__ float g_attn[(long)NB * NHEADS * NPIX * NPIX];// 256 MB attention logits/probs
__device__ float g_ao  [NB * NC * NPIX];                 // 32 MB  attention output

// ---------------------------------------------------------------------------
// GroupNorm: one block per (batch, group). Group = 16 channels x 1024 pixels.
// ---------------------------------------------------------------------------
__global__ __launch_bounds__(256) void groupnorm_k(
    const float* __restrict__ x, const float* __restrict__ w,
    const float* __restrict__ bgn, float* __restrict__ h)
{
    const int CH_PER_G = NC / NGROUPS;        // 16
    const int GE = CH_PER_G * NPIX;           // 16384
    int b = blockIdx.x >> 5;
    int g = blockIdx.x & 31;
    long base = ((long)b * NC + (long)g * CH_PER_G) * NPIX;
    const float* xp = x + base;
    float* hp = h + base;

    float s = 0.f, s2 = 0.f;
    for (int i = threadIdx.x; i < GE; i += 256) {
        float v = xp[i];
        s += v; s2 += v * v;
    }
    __shared__ float r0[256], r1[256];
    r0[threadIdx.x] = s; r1[threadIdx.x] = s2;
    __syncthreads();
    for (int o = 128; o > 0; o >>= 1) {
        if (threadIdx.x < o) {
            r0[threadIdx.x] += r0[threadIdx.x + o];
            r1[threadIdx.x] += r1[threadIdx.x + o];
        }
        __syncthreads();
    }
    float mu  = r0[0] * (1.f / GE);
    float var = r1[0] * (1.f / GE) - mu * mu;
    float inv = rsqrtf(var + 1e-5f);

    for (int i = threadIdx.x; i < GE; i += 256) {
        int c = g * CH_PER_G + (i >> 10);
        hp[i] = (xp[i] - mu) * inv * w[c] + bgn[c];
    }
}

// ---------------------------------------------------------------------------
// Generic batched tiled SGEMM.  C[m,n] = epi( sum_k A[m,k] * B[k,n] )
// Block tile 64x64, K-tile 16, 256 threads, 4x4 per-thread microtile.
// A_KC:  A is K-contiguous (sAk == 1)        -> coalesce along k
// B_NC:  B is N-contiguous (sBn == 1)        -> coalesce along n
// C is always written row-major with ld = NPIX (1024).
// Batch offset = (z / INNER)*Outer + (z % INNER)*Inner  for each operand.
// ---------------------------------------------------------------------------
template<bool A_KC, bool B_NC, bool HAS_BIAS, bool HAS_RES, bool HAS_SCALE>
__global__ __launch_bounds__(256) void gemm64(
    const float* __restrict__ A, const float* __restrict__ Bm,
    const float* __restrict__ bias, const float* __restrict__ res,
    float* __restrict__ Cp,
    int K,
    long sAm, long sAk, long aO, long aI,
    long sBk, long sBn, long bO, long bI,
    long cO,  long cI,  long rO, long rI,
    int INNER, float scale)
{
    __shared__ float As[16][68];
    __shared__ float Bs[16][68];

    int z  = blockIdx.z;
    int zo = z / INNER, zi = z - zo * INNER;
    const float* Ab = A  + (long)zo * aO + (long)zi * aI;
    const float* Bb = Bm + (long)zo * bO + (long)zi * bI;
    float*       Cb = Cp + (long)zo * cO + (long)zi * cI;
    const float* Rb = HAS_RES ? (res + (long)zo * rO + (long)zi * rI) : nullptr;

    int m0 = blockIdx.y * 64, n0 = blockIdx.x * 64;
    int tid = threadIdx.x;
    int tx = tid & 15, ty = tid >> 4;

    float acc[4][4] = {};

    for (int k0 = 0; k0 < K; k0 += 16) {
        #pragma unroll
        for (int l = 0; l < 4; l++) {
            int e = tid + l * 256;
            int m, kk;
            if (A_KC) { kk = e & 15; m = e >> 4; }
            else      { m  = e & 63; kk = e >> 6; }
            As[kk][m] = Ab[(long)(m0 + m) * sAm + (long)(k0 + kk) * sAk];

            int n, kb;
            if (B_NC) { n  = e & 63; kb = e >> 6; }
            else      { kb = e & 15; n  = e >> 4; }
            Bs[kb][n] = Bb[(long)(k0 + kb) * sBk + (long)(n0 + n) * sBn];
        }
        __syncthreads();

        #pragma unroll
        for (int kk = 0; kk < 16; kk++) {
            float4 a4 = *(const float4*)&As[kk][ty * 4];
            float4 b4 = *(const float4*)&Bs[kk][tx * 4];
            float av[4] = {a4.x, a4.y, a4.z, a4.w};
            float bv[4] = {b4.x, b4.y, b4.z, b4.w};
            #pragma unroll
            for (int i = 0; i < 4; i++)
                #pragma unroll
                for (int j = 0; j < 4; j++)
                    acc[i][j] = fmaf(av[i], bv[j], acc[i][j]);
        }
        __syncthreads();
    }

    #pragma unroll
    for (int i = 0; i < 4; i++) {
        int m = m0 + ty * 4 + i;
        long off = (long)m * NPIX + n0 + tx * 4;
        float4 o;
        o.x = acc[i][0]; o.y = acc[i][1]; o.z = acc[i][2]; o.w = acc[i][3];
        if (HAS_SCALE) { o.x *= scale; o.y *= scale; o.z *= scale; o.w *= scale; }
        if (HAS_BIAS) {
            float bsv = bias[m];
            o.x += bsv; o.y += bsv; o.z += bsv; o.w += bsv;
        }
        if (HAS_RES) {
            float4 r4 = *(const float4*)&Rb[off];
            o.x += r4.x; o.y += r4.y; o.z += r4.z; o.w += r4.w;
        }
        *(float4*)&Cb[off] = o;
    }
}

// ---------------------------------------------------------------------------
// Row softmax over 1024-wide rows, values held in registers.
// ---------------------------------------------------------------------------
__global__ __launch_bounds__(128) void softmax_k(float* __restrict__ p)
{
    float* row = p + (long)blockIdx.x * NPIX;
    int t = threadIdx.x;
    float v[8];
    float mx = -1e30f;
    #pragma unroll
    for (int i = 0; i < 8; i++) {
        v[i] = row[t + i * 128];
        mx = fmaxf(mx, v[i]);
    }
    __shared__ float sm[128];
    sm[t] = mx; __syncthreads();
    for (int o = 64; o > 0; o >>= 1) {
        if (t < o) sm[t] = fmaxf(sm[t], sm[t + o]);
        __syncthreads();
    }
    mx = sm[0];
    __syncthreads();

    float s = 0.f;
    #pragma unroll
    for (int i = 0; i < 8; i++) {
        v[i] = __expf(v[i] - mx);
        s += v[i];
    }
    sm[t] = s; __syncthreads();
    for (int o = 64; o > 0; o >>= 1) {
        if (t < o) sm[t] += sm[t + o];
        __syncthreads();
    }
    float inv = 1.f / sm[0];
    #pragma unroll
    for (int i = 0; i < 8; i++)
        row[t + i * 128] = v[i] * inv;
}

// ---------------------------------------------------------------------------
// kernel_launch
// Inputs (metadata order): x, norm_w, norm_b, qkv_w, qkv_b, proj_w, proj_b
// ---------------------------------------------------------------------------
extern "C" void kernel_launch(void* const* d_in, const int* in_sizes, int n_in,
                              void* d_out, int out_size)
{
    const float* x      = (const float*)d_in[0];
    const float* norm_w = (const float*)d_in[1];
    const float* norm_b = (const float*)d_in[2];
    const float* qkv_w  = (const float*)d_in[3];
    const float* qkv_b  = (const float*)d_in[4];
    const float* proj_w = (const float*)d_in[5];
    const float* proj_b = (const float*)d_in[6];
    float* out = (float*)d_out;

    float *h, *qkv, *attn, *ao;
    cudaGetSymbolAddress((void**)&h,    g_h);
    cudaGetSymbolAddress((void**)&qkv,  g_qkv);
    cudaGetSymbolAddress((void**)&attn, g_attn);
    cudaGetSymbolAddress((void**)&ao,   g_ao);

    const long CN  = (long)NC * NPIX;          // 524288
    const long C3N = 3 * CN;                   // 1572864
    const long HN  = (long)HD * NPIX;          // 131072
    const long NN  = (long)NPIX * NPIX;        // 1048576
    const float scale = 0.08838834764831845f;  // 128^-0.5

    // 1) GroupNorm
    groupnorm_k<<<NB * NGROUPS, 256>>>(x, norm_w, norm_b, h);

    // 2) QKV: per-batch (1536 x 1024) = W(1536x512) @ h(512x1024) + bias
    gemm64<true, true, true, false, false><<<dim3(16, 24, NB), 256>>>(
        qkv_w, h, qkv_b, nullptr, qkv,
        /*K=*/NC,
        /*A*/ 512, 1, 0, 0,
        /*B*/ NPIX, 1, CN, 0,
        /*C*/ (long)1536 * NPIX, 0,
        /*R*/ 0, 0,
        /*INNER*/ 1, 0.f);

    // 3) Scores: per (b,h): S(1024x1024) = scale * Q^T(1024x128) @ K(128x1024)
    gemm64<false, true, false, false, true><<<dim3(16, 16, NB * NHEADS), 256>>>(
        qkv, qkv + CN, nullptr, nullptr, attn,
        /*K=*/HD,
        /*A*/ 1, NPIX, C3N, HN,
        /*B*/ NPIX, 1, C3N, HN,
        /*C*/ (long)NHEADS * NN, NN,
        /*R*/ 0, 0,
        /*INNER*/ NHEADS, scale);

    // 4) Softmax over rows
    softmax_k<<<NB * NHEADS * NPIX, 128>>>(attn);

    // 5) PV: per (b,h): O(128x1024) = V(128x1024) @ P^T(1024x1024)
    gemm64<true, false, false, false, false><<<dim3(16, 2, NB * NHEADS), 256>>>(
        qkv + 2 * CN, attn, nullptr, nullptr, ao,
        /*K=*/NPIX,
        /*A*/ NPIX, 1, C3N, HN,
        /*B*/ 1, NPIX, (long)NHEADS * NN, NN,
        /*C*/ CN, HN,
        /*R*/ 0, 0,
        /*INNER*/ NHEADS, 0.f);

    // 6) Proj + bias + residual: out = x + W(512x512) @ ao(512x1024) + b
    gemm64<true, true, true, true, false><<<dim3(16, 8, NB), 256>>>(
        proj_w, ao, proj_b, x, out,
        /*K=*/NC,
        /*A*/ 512, 1, 0, 0,
        /*B*/ NPIX, 1, CN, 0,
        /*C*/ CN, 0,
        /*R*/ CN, 0,
        /*INNER*/ 1, 0.f);
}

// round 11
// speedup vs baseline: 2.8242x; 2.8242x over previous
#include <cuda_runtime.h>
#include <cstdint>
#include <math.h>

// Problem constants
#define NB    16
#define NC    512
#define NPIX  1024          // H*W
#define NHEADS 4
#define HD    128
#define NGROUPS 32

// Scratch (device globals; allocation-free contract)
__device__ float g_ht  [(size_t)NB * NPIX * NC];            // 32 MB  h transposed [b][n][c]
__device__ float g_qkvt[(size_t)NB * NPIX * 3 * NC];        // 100 MB qkv transposed [b][n][1536]
__device__ float g_attn[(size_t)NB * NHEADS * NPIX * NPIX]; // 256 MB attention
__device__ float g_vt  [(size_t)NB * NC * NPIX];            // 32 MB  v transposed [b][h][hd][m]
__device__ float g_aot [(size_t)NB * NPIX * NC];            // 32 MB  attn out [b][n][c]

// ---------------------------------------------------------------------------
// Helpers (all sm_80+ baseline PTX — NO sm_103a-only features)
// ---------------------------------------------------------------------------
__device__ __forceinline__ uint32_t smem_u32(const void* p) {
    uint32_t a;
    asm("{ .reg .u64 t; cvta.to.shared.u64 t, %1; cvt.u32.u64 %0, t; }"
        : "=r"(a) : "l"(p));
    return a;
}
__device__ __forceinline__ uint32_t f2tf(float x) {
    uint32_t r;
    asm("cvt.rna.tf32.f32 %0, %1;" : "=r"(r) : "f"(x));
    return r;
}
__device__ __forceinline__ void mma1688(float* d, const uint32_t* a, const uint32_t* b) {
    asm volatile(
        "mma.sync.aligned.m16n8k8.row.col.f32.tf32.tf32.f32 "
        "{%0,%1,%2,%3}, {%4,%5,%6,%7}, {%8,%9}, {%0,%1,%2,%3};"
        : "+f"(d[0]), "+f"(d[1]), "+f"(d[2]), "+f"(d[3])
        : "r"(a[0]), "r"(a[1]), "r"(a[2]), "r"(a[3]), "r"(b[0]), "r"(b[1]));
}
#define CP_ASYNC16(dst, src) \
    asm volatile("cp.async.cg.shared.global [%0], [%1], 16;" :: "r"(dst), "l"(src))
#define CP_COMMIT() asm volatile("cp.async.commit_group;" ::: "memory")
#define CP_WAIT1()  asm volatile("cp.async.wait_group 1;" ::: "memory")
#define CP_WAIT0()  asm volatile("cp.async.wait_group 0;" ::: "memory")

// ---------------------------------------------------------------------------
// GroupNorm writing TRANSPOSED output h_t[b][n][c] (pixel-major).
// One block per (batch, group); group = 16 channels x 1024 pixels.
// ---------------------------------------------------------------------------
__global__ __launch_bounds__(256) void groupnorm_t_k(
    const float* __restrict__ x, const float* __restrict__ w,
    const float* __restrict__ bgn, float* __restrict__ ht)
{
    __shared__ float r0[256], r1[256];
    __shared__ float tile[16][65];
    int b = blockIdx.x >> 5;
    int g = blockIdx.x & 31;
    int gc = g * 16;
    const float* xp = x + ((long)b * NC + gc) * NPIX;
    float* hp = ht + (long)b * NPIX * NC;

    float s = 0.f, s2 = 0.f;
    for (int i = threadIdx.x; i < 16 * NPIX; i += 256) {
        float v = xp[i];
        s += v; s2 += v * v;
    }
    r0[threadIdx.x] = s; r1[threadIdx.x] = s2;
    __syncthreads();
    for (int o = 128; o > 0; o >>= 1) {
        if (threadIdx.x < o) {
            r0[threadIdx.x] += r0[threadIdx.x + o];
            r1[threadIdx.x] += r1[threadIdx.x + o];
        }
        __syncthreads();
    }
    const float GEinv = 1.f / (16.f * NPIX);
    float mu  = r0[0] * GEinv;
    float var = r1[0] * GEinv - mu * mu;
    float inv = rsqrtf(var + 1e-5f);

    for (int n0s = 0; n0s < NPIX; n0s += 64) {
        __syncthreads();
        #pragma unroll
        for (int t = 0; t < 4; ++t) {
            int i = threadIdx.x + t * 256;
            int c = i >> 6, nn = i & 63;
            tile[c][nn] = xp[(long)c * NPIX + n0s + nn];
        }
        __syncthreads();
        #pragma unroll
        for (int t = 0; t < 4; ++t) {
            int i = threadIdx.x + t * 256;
            int c = i & 15, nn = i >> 4;
            int ch = gc + c;
            hp[(long)(n0s + nn) * NC + ch] =
                (tile[c][nn] - mu) * inv * w[ch] + bgn[ch];
        }
    }
}

// ---------------------------------------------------------------------------
// V transpose: v_t[b][c2][m] = qkv_t[b][m][1024 + c2]   (c2 = h*128+hd)
// ---------------------------------------------------------------------------
__global__ __launch_bounds__(256) void transpose_v_k(
    const float* __restrict__ q, float* __restrict__ vt)
{
    __shared__ float t[32][33];
    int b = blockIdx.z;
    const float* in = q + (long)b * 3 * NC * NPIX + 2 * NC;  // V section
    float* out = vt + (long)b * NC * NPIX;
    int m0 = blockIdx.x * 32, c0 = blockIdx.y * 32;
    int tx = threadIdx.x & 31, ty = threadIdx.x >> 5;
    #pragma unroll
    for (int j = ty; j < 32; j += 8)
        t[j][tx] = in[(long)(m0 + j) * (3 * NC) + c0 + tx];
    __syncthreads();
    #pragma unroll
    for (int j = ty; j < 32; j += 8)
        out[(long)(c0 + j) * NPIX + m0 + tx] = t[tx][j];
}

// ---------------------------------------------------------------------------
// tf32 HMMA GEMM:  C[m,n] = epi( sum_k A[m0+m, k] * B[n0+n, k] )
// A: M x K (K contiguous, lda).  B: N x K (K contiguous, ldb).  C row-major ldc.
// Block tile 128x128, 8 warps (2x4), warp tile 64x32 via 4x4 m16n8k8 mmas.
// K-chunks of 16 floats, cp.async double-buffered.
// Batch offset = zo*Outer + zi*Inner per operand (z = blockIdx.z).
// ---------------------------------------------------------------------------
template<bool BCOL, bool BROW, bool HAS_RES, bool HAS_SCALE>
__global__ __launch_bounds__(256) void gemm_tc(
    const float* __restrict__ A, const float* __restrict__ B,
    const float* __restrict__ bias, const float* __restrict__ res,
    float* __restrict__ C,
    int K, long lda, long ldb, long ldc,
    long aO, long aI, long bO, long bI,
    long cO, long cI, long rO, long rI,
    int INNER, float scale)
{
    __shared__ float As[2][128][20];   // stride 20 -> conflict-free fragments
    __shared__ float Bs[2][128][20];

    const int tid = threadIdx.x;
    const int wid = tid >> 5, lane = tid & 31;
    const int wm = wid & 1, wn = wid >> 1;    // 2 x 4 warp grid
    const int lr = lane >> 2, lc = lane & 3;

    int z = blockIdx.z, zo = z / INNER, zi = z - zo * INNER;
    const float* Ab = A + (long)zo * aO + (long)zi * aI;
    const float* Bb = B + (long)zo * bO + (long)zi * bI;
    float*       Cb = C + (long)zo * cO + (long)zi * cI;
    const float* Rb = HAS_RES ? (res + (long)zo * rO + (long)zi * rI) : nullptr;
    const int n0 = blockIdx.x * 128, m0 = blockIdx.y * 128;

    float acc[4][4][4];
    #pragma unroll
    for (int i = 0; i < 4; ++i)
        #pragma unroll
        for (int j = 0; j < 4; ++j)
            #pragma unroll
            for (int q = 0; q < 4; ++q) acc[i][j][q] = 0.f;

    const int nch = K >> 4;

    // stage chunk c into buffer p
    auto stage = [&](int p, int c) {
        long k0 = (long)c << 4;
        #pragma unroll
        for (int l = 0; l < 2; ++l) {
            int e = tid + l * 256;
            int row = e >> 2, kq = (e & 3) << 2;
            CP_ASYNC16(smem_u32(&As[p][row][kq]),
                       Ab + (long)(m0 + row) * lda + k0 + kq);
            CP_ASYNC16(smem_u32(&Bs[p][row][kq]),
                       Bb + (long)(n0 + row) * ldb + k0 + kq);
        }
        CP_COMMIT();
    };

    stage(0, 0);

    for (int c = 0; c < nch; ++c) {
        const int p = c & 1;
        if (c + 1 < nch) { stage(p ^ 1, c + 1); CP_WAIT1(); }
        else             { CP_WAIT0(); }
        __syncthreads();

        const float (*A_s)[20] = As[p];
        const float (*B_s)[20] = Bs[p];
        #pragma unroll
        for (int ks = 0; ks < 16; ks += 8) {
            uint32_t af[4][4], bf[4][2];
            #pragma unroll
            for (int i = 0; i < 4; ++i) {
                int mi = wm * 64 + i * 16 + lr;
                af[i][0] = f2tf(A_s[mi    ][ks + lc]);
                af[i][1] = f2tf(A_s[mi + 8][ks + lc]);
                af[i][2] = f2tf(A_s[mi    ][ks + 4 + lc]);
                af[i][3] = f2tf(A_s[mi + 8][ks + 4 + lc]);
            }
            #pragma unroll
            for (int j = 0; j < 4; ++j) {
                int nj = wn * 32 + j * 8 + lr;
                bf[j][0] = f2tf(B_s[nj][ks + lc]);
                bf[j][1] = f2tf(B_s[nj][ks + 4 + lc]);
            }
            #pragma unroll
            for (int i = 0; i < 4; ++i)
                #pragma unroll
                for (int j = 0; j < 4; ++j)
                    mma1688(acc[i][j], af[i], bf[j]);
        }
        __syncthreads();
    }

    // Epilogue
    #pragma unroll
    for (int i = 0; i < 4; ++i) {
        int m = m0 + wm * 64 + i * 16 + lr;
        float br0 = BROW ? __ldg(bias + m)     : 0.f;
        float br1 = BROW ? __ldg(bias + m + 8) : 0.f;
        #pragma unroll
        for (int j = 0; j < 4; ++j) {
            int n = n0 + wn * 32 + j * 8 + 2 * lc;
            float2 v0 = make_float2(acc[i][j][0], acc[i][j][1]);
            float2 v1 = make_float2(acc[i][j][2], acc[i][j][3]);
            if (HAS_SCALE) {
                v0.x *= scale; v0.y *= scale; v1.x *= scale; v1.y *= scale;
            }
            if (BCOL) {
                float2 bc = *(const float2*)(bias + n);
                v0.x += bc.x; v0.y += bc.y; v1.x += bc.x; v1.y += bc.y;
            }
            if (BROW) {
                v0.x += br0; v0.y += br0; v1.x += br1; v1.y += br1;
            }
            long off0 = (long)m * ldc + n;
            long off1 = (long)(m + 8) * ldc + n;
            if (HAS_RES) {
                float2 r0v = *(const float2*)(Rb + off0);
                float2 r1v = *(const float2*)(Rb + off1);
                v0.x += r0v.x; v0.y += r0v.y; v1.x += r1v.x; v1.y += r1v.y;
            }
            *(float2*)(Cb + off0) = v0;
            *(float2*)(Cb + off1) = v1;
        }
    }
}

// ---------------------------------------------------------------------------
// Row softmax over 1024-wide rows, values held in registers.
// ---------------------------------------------------------------------------
__global__ __launch_bounds__(128) void softmax_k(float* __restrict__ p)
{
    float* row = p + (long)blockIdx.x * NPIX;
    int t = threadIdx.x;
    float v[8];
    float mx = -1e30f;
    #pragma unroll
    for (int i = 0; i < 8; i++) {
        v[i] = row[t + i * 128];
        mx = fmaxf(mx, v[i]);
    }
    __shared__ float sm[128];
    sm[t] = mx; __syncthreads();
    for (int o = 64; o > 0; o >>= 1) {
        if (t < o) sm[t] = fmaxf(sm[t], sm[t + o]);
        __syncthreads();
    }
    mx = sm[0];
    __syncthreads();

    float s = 0.f;
    #pragma unroll
    for (int i = 0; i < 8; i++) {
        v[i] = __expf(v[i] - mx);
        s += v[i];
    }
    sm[t] = s; __syncthreads();
    for (int o = 64; o > 0; o >>= 1) {
        if (t < o) sm[t] += sm[t + o];
        __syncthreads();
    }
    float inv = 1.f / sm[0];
    #pragma unroll
    for (int i = 0; i < 8; i++)
        row[t + i * 128] = v[i] * inv;
}

// ---------------------------------------------------------------------------
// kernel_launch
// Inputs: x, norm_w, norm_b, qkv_w, qkv_b, proj_w, proj_b
// ---------------------------------------------------------------------------
extern "C" void kernel_launch(void* const* d_in, const int* in_sizes, int n_in,
                              void* d_out, int out_size)
{
    const float* x      = (const float*)d_in[0];
    const float* norm_w = (const float*)d_in[1];
    const float* norm_b = (const float*)d_in[2];
    const float* qkv_w  = (const float*)d_in[3];
    const float* qkv_b  = (const float*)d_in[4];
    const float* proj_w = (const float*)d_in[5];
    const float* proj_b = (const float*)d_in[6];
    float* out = (float*)d_out;

    float *ht, *qkvt, *attn, *vt, *aot;
    cudaGetSymbolAddress((void**)&ht,   g_ht);
    cudaGetSymbolAddress((void**)&qkvt, g_qkvt);
    cudaGetSymbolAddress((void**)&attn, g_attn);
    cudaGetSymbolAddress((void**)&vt,   g_vt);
    cudaGetSymbolAddress((void**)&aot,  g_aot);

    const long CN  = (long)NC * NPIX;            // 524288
    const long C3N = 3 * CN;                     // 1572864 (qkv_t per batch)
    const long HN  = (long)HD * NPIX;            // 131072
    const long NN  = (long)NPIX * NPIX;          // 1048576
    const float scale = 0.08838834764831845f;    // 128^-0.5

    // 1) GroupNorm -> h_t[b][n][c]
    groupnorm_t_k<<<NB * NGROUPS, 256>>>(x, norm_w, norm_b, ht);

    // 2) QKV: per batch  qkv_t[n, o] = h_t[n, :] . qkv_w[o, :]  + bias[o]
    //    M=1024, N=1536, K=512
    gemm_tc<true, false, false, false><<<dim3(12, 8, NB), 256>>>(
        ht, qkv_w, qkv_b, nullptr, qkvt,
        /*K*/ 512, /*lda*/ 512, /*ldb*/ 512, /*ldc*/ 1536,
        /*a*/ CN, 0, /*b*/ 0, 0, /*c*/ C3N, 0, /*r*/ 0, 0,
        /*INNER*/ 1, 0.f);

    // 3) V transpose -> v_t[b][c2][m]
    transpose_v_k<<<dim3(32, 16, NB), 256>>>(qkvt, vt);

    // 4) Scores: per (b,h)  S[n, m] = scale * Q[n,:] . K[m,:]
    //    M=1024, N=1024, K=128
    gemm_tc<false, false, false, true><<<dim3(8, 8, NB * NHEADS), 256>>>(
        qkvt, qkvt + NC, nullptr, nullptr, attn,
        /*K*/ 128, /*lda*/ 1536, /*ldb*/ 1536, /*ldc*/ 1024,
        /*a*/ C3N, HD, /*b*/ C3N, HD, /*c*/ (long)NHEADS * NN, NN, /*r*/ 0, 0,
        /*INNER*/ NHEADS, scale);

    // 5) Softmax over rows
    softmax_k<<<NB * NHEADS * NPIX, 128>>>(attn);

    // 6) PV: per (b,h)  ao_t[n, h*128+j] = P[n,:] . v_t[j,:]
    //    M=1024, N=128, K=1024
    gemm_tc<false, false, false, false><<<dim3(1, 8, NB * NHEADS), 256>>>(
        attn, vt, nullptr, nullptr, aot,
        /*K*/ 1024, /*lda*/ 1024, /*ldb*/ 1024, /*ldc*/ 512,
        /*a*/ (long)NHEADS * NN, NN, /*b*/ CN, HN, /*c*/ CN, HD, /*r*/ 0, 0,
        /*INNER*/ NHEADS, 0.f);

    // 7) Proj + bias + residual: per batch  out[co, n] = proj_w[co,:] . ao_t[n,:] + b[co] + x[co,n]
    //    M=512, N=1024, K=512
    gemm_tc<false, true, true, false><<<dim3(8, 4, NB), 256>>>(
        proj_w, aot, proj_b, x, out,
        /*K*/ 512, /*lda*/ 512, /*ldb*/ 512, /*ldc*/ 1024,
        /*a*/ 0, 0, /*b*/ CN, 0, /*c*/ CN, 0, /*r*/ CN, 0,
        /*INNER*/ 1, 0.f);
}

// round 14
// speedup vs baseline: 3.1814x; 1.1265x over previous
#include <cuda_runtime.h>
#include <cstdint>
#include <math.h>

// Problem constants
#define NB    16
#define NC    512
#define NPIX  1024          // H*W
#define NHEADS 4
#define HD    128
#define NGROUPS 32

// Scratch (device globals; allocation-free contract)
__device__ float g_ht  [(size_t)NB * NPIX * NC];            // 32 MB  h transposed [b][n][c]
__device__ float g_qkvt[(size_t)NB * NPIX * 3 * NC];        // 100 MB qkv transposed [b][n][1536]
__device__ float g_vt  [(size_t)NB * NC * NPIX];            // 32 MB  v transposed [b][h][hd][m]
__device__ float g_aot [(size_t)NB * NPIX * NC];            // 32 MB  attn out [b][n][c]
__device__ float g_wq  [3 * NC * NC];                       // rounded qkv_w
__device__ float g_wp  [NC * NC];                           // rounded proj_w

// ---------------------------------------------------------------------------
// Helpers (all sm_80+ baseline PTX — NO sm_103a-only features)
// ---------------------------------------------------------------------------
__device__ __forceinline__ uint32_t smem_u32(const void* p) {
    uint32_t a;
    asm("{ .reg .u64 t; cvta.to.shared.u64 t, %1; cvt.u32.u64 %0, t; }"
        : "=r"(a) : "l"(p));
    return a;
}
__device__ __forceinline__ uint32_t f2tf(float x) {
    uint32_t r;
    asm("cvt.rna.tf32.f32 %0, %1;" : "=r"(r) : "f"(x));
    return r;
}
__device__ __forceinline__ float rndf(float x) { return __uint_as_float(f2tf(x)); }

__device__ __forceinline__ void mma1688(float* d, const uint32_t* a, const uint32_t* b) {
    asm volatile(
        "mma.sync.aligned.m16n8k8.row.col.f32.tf32.tf32.f32 "
        "{%0,%1,%2,%3}, {%4,%5,%6,%7}, {%8,%9}, {%0,%1,%2,%3};"
        : "+f"(d[0]), "+f"(d[1]), "+f"(d[2]), "+f"(d[3])
        : "r"(a[0]), "r"(a[1]), "r"(a[2]), "r"(a[3]), "r"(b[0]), "r"(b[1]));
}
#define CP_ASYNC16(dst, src) \
    asm volatile("cp.async.cg.shared.global [%0], [%1], 16;" :: "r"(dst), "l"(src))
#define CP_COMMIT() asm volatile("cp.async.commit_group;" ::: "memory")
#define CP_WAIT1()  asm volatile("cp.async.wait_group 1;" ::: "memory")
#define CP_WAIT0()  asm volatile("cp.async.wait_group 0;" ::: "memory")

// ---------------------------------------------------------------------------
// Round-copy (pre-round weights to tf32 so GEMM inner loops skip cvt)
// ---------------------------------------------------------------------------
__global__ __launch_bounds__(256) void round_copy_k(
    const float* __restrict__ in, float* __restrict__ out, int n)
{
    int i = blockIdx.x * 256 + threadIdx.x;
    if (i < n) out[i] = rndf(in[i]);
}

// ---------------------------------------------------------------------------
// GroupNorm writing TRANSPOSED, tf32-rounded output h_t[b][n][c].
// ---------------------------------------------------------------------------
__global__ __launch_bounds__(256) void groupnorm_t_k(
    const float* __restrict__ x, const float* __restrict__ w,
    const float* __restrict__ bgn, float* __restrict__ ht)
{
    __shared__ float r0[256], r1[256];
    __shared__ float tile[16][65];
    int b = blockIdx.x >> 5;
    int g = blockIdx.x & 31;
    int gc = g * 16;
    const float* xp = x + ((long)b * NC + gc) * NPIX;
    float* hp = ht + (long)b * NPIX * NC;

    float s = 0.f, s2 = 0.f;
    for (int i = threadIdx.x; i < 16 * NPIX; i += 256) {
        float v = xp[i];
        s += v; s2 += v * v;
    }
    r0[threadIdx.x] = s; r1[threadIdx.x] = s2;
    __syncthreads();
    for (int o = 128; o > 0; o >>= 1) {
        if (threadIdx.x < o) {
            r0[threadIdx.x] += r0[threadIdx.x + o];
            r1[threadIdx.x] += r1[threadIdx.x + o];
        }
        __syncthreads();
    }
    const float GEinv = 1.f / (16.f * NPIX);
    float mu  = r0[0] * GEinv;
    float var = r1[0] * GEinv - mu * mu;
    float inv = rsqrtf(var + 1e-5f);

    for (int n0s = 0; n0s < NPIX; n0s += 64) {
        __syncthreads();
        #pragma unroll
        for (int t = 0; t < 4; ++t) {
            int i = threadIdx.x + t * 256;
            int c = i >> 6, nn = i & 63;
            tile[c][nn] = xp[(long)c * NPIX + n0s + nn];
        }
        __syncthreads();
        #pragma unroll
        for (int t = 0; t < 4; ++t) {
            int i = threadIdx.x + t * 256;
            int c = i & 15, nn = i >> 4;
            int ch = gc + c;
            hp[(long)(n0s + nn) * NC + ch] =
                rndf((tile[c][nn] - mu) * inv * w[ch] + bgn[ch]);
        }
    }
}

// ---------------------------------------------------------------------------
// V transpose: v_t[b][c2][m] = qkv_t[b][m][1024 + c2]
// ---------------------------------------------------------------------------
__global__ __launch_bounds__(256) void transpose_v_k(
    const float* __restrict__ q, float* __restrict__ vt)
{
    __shared__ float t[32][33];
    int b = blockIdx.z;
    const float* in = q + (long)b * 3 * NC * NPIX + 2 * NC;  // V section
    float* out = vt + (long)b * NC * NPIX;
    int m0 = blockIdx.x * 32, c0 = blockIdx.y * 32;
    int tx = threadIdx.x & 31, ty = threadIdx.x >> 5;
    #pragma unroll
    for (int j = ty; j < 32; j += 8)
        t[j][tx] = in[(long)(m0 + j) * (3 * NC) + c0 + tx];
    __syncthreads();
    #pragma unroll
    for (int j = ty; j < 32; j += 8)
        out[(long)(c0 + j) * NPIX + m0 + tx] = t[tx][j];
}

// ---------------------------------------------------------------------------
// tf32 HMMA GEMM (inputs MUST already be tf32-rounded; raw bits fed to MMA).
// C[m,n] = epi( sum_k A[m0+m, k] * B[n0+n, k] )
// ---------------------------------------------------------------------------
template<bool BCOL, bool BROW, bool HAS_RES, bool HAS_SCALE, bool ROUND>
__global__ __launch_bounds__(256) void gemm_tc(
    const float* __restrict__ A, const float* __restrict__ B,
    const float* __restrict__ bias, const float* __restrict__ res,
    float* __restrict__ C,
    int K, long lda, long ldb, long ldc,
    long aO, long aI, long bO, long bI,
    long cO, long cI, long rO, long rI,
    int INNER, float scale)
{
    __shared__ float As[2][128][20];
    __shared__ float Bs[2][128][20];

    const int tid = threadIdx.x;
    const int wid = tid >> 5, lane = tid & 31;
    const int wm = wid & 1, wn = wid >> 1;    // 2 x 4 warp grid
    const int lr = lane >> 2, lc = lane & 3;

    int z = blockIdx.z, zo = z / INNER, zi = z - zo * INNER;
    const float* Ab = A + (long)zo * aO + (long)zi * aI;
    const float* Bb = B + (long)zo * bO + (long)zi * bI;
    float*       Cb = C + (long)zo * cO + (long)zi * cI;
    const float* Rb = HAS_RES ? (res + (long)zo * rO + (long)zi * rI) : nullptr;
    const int n0 = blockIdx.x * 128, m0 = blockIdx.y * 128;

    float acc[4][4][4];
    #pragma unroll
    for (int i = 0; i < 4; ++i)
        #pragma unroll
        for (int j = 0; j < 4; ++j)
            #pragma unroll
            for (int q = 0; q < 4; ++q) acc[i][j][q] = 0.f;

    const int nch = K >> 4;

    auto stage = [&](int p, int c) {
        long k0 = (long)c << 4;
        #pragma unroll
        for (int l = 0; l < 2; ++l) {
            int e = tid + l * 256;
            int row = e >> 2, kq = (e & 3) << 2;
            CP_ASYNC16(smem_u32(&As[p][row][kq]),
                       Ab + (long)(m0 + row) * lda + k0 + kq);
            CP_ASYNC16(smem_u32(&Bs[p][row][kq]),
                       Bb + (long)(n0 + row) * ldb + k0 + kq);
        }
        CP_COMMIT();
    };

    stage(0, 0);

    for (int c = 0; c < nch; ++c) {
        const int p = c & 1;
        if (c + 1 < nch) { stage(p ^ 1, c + 1); CP_WAIT1(); }
        else             { CP_WAIT0(); }
        __syncthreads();

        const float (*A_s)[20] = As[p];
        const float (*B_s)[20] = Bs[p];
        #pragma unroll
        for (int ks = 0; ks < 16; ks += 8) {
            uint32_t af[4][4], bf[4][2];
            #pragma unroll
            for (int i = 0; i < 4; ++i) {
                int mi = wm * 64 + i * 16 + lr;
                af[i][0] = __float_as_uint(A_s[mi    ][ks + lc]);
                af[i][1] = __float_as_uint(A_s[mi + 8][ks + lc]);
                af[i][2] = __float_as_uint(A_s[mi    ][ks + 4 + lc]);
                af[i][3] = __float_as_uint(A_s[mi + 8][ks + 4 + lc]);
            }
            #pragma unroll
            for (int j = 0; j < 4; ++j) {
                int nj = wn * 32 + j * 8 + lr;
                bf[j][0] = __float_as_uint(B_s[nj][ks + lc]);
                bf[j][1] = __float_as_uint(B_s[nj][ks + 4 + lc]);
            }
            #pragma unroll
            for (int i = 0; i < 4; ++i)
                #pragma unroll
                for (int j = 0; j < 4; ++j)
                    mma1688(acc[i][j], af[i], bf[j]);
        }
        __syncthreads();
    }

    // Epilogue
    #pragma unroll
    for (int i = 0; i < 4; ++i) {
        int m = m0 + wm * 64 + i * 16 + lr;
        float br0 = BROW ? __ldg(bias + m)     : 0.f;
        float br1 = BROW ? __ldg(bias + m + 8) : 0.f;
        #pragma unroll
        for (int j = 0; j < 4; ++j) {
            int n = n0 + wn * 32 + j * 8 + 2 * lc;
            float2 v0 = make_float2(acc[i][j][0], acc[i][j][1]);
            float2 v1 = make_float2(acc[i][j][2], acc[i][j][3]);
            if (HAS_SCALE) {
                v0.x *= scale; v0.y *= scale; v1.x *= scale; v1.y *= scale;
            }
            if (BCOL) {
                float2 bc = *(const float2*)(bias + n);
                v0.x += bc.x; v0.y += bc.y; v1.x += bc.x; v1.y += bc.y;
            }
            if (BROW) {
                v0.x += br0; v0.y += br0; v1.x += br1; v1.y += br1;
            }
            long off0 = (long)m * ldc + n;
            long off1 = (long)(m + 8) * ldc + n;
            if (HAS_RES) {
                float2 r0v = *(const float2*)(Rb + off0);
                float2 r1v = *(const float2*)(Rb + off1);
                v0.x += r0v.x; v0.y += r0v.y; v1.x += r1v.x; v1.y += r1v.y;
            }
            if (ROUND) {
                v0.x = rndf(v0.x); v0.y = rndf(v0.y);
                v1.x = rndf(v1.x); v1.y = rndf(v1.y);
            }
            *(float2*)(Cb + off0) = v0;
            *(float2*)(Cb + off1) = v1;
        }
    }
}

// ---------------------------------------------------------------------------
// Flash attention: one block per (128-query tile, b*h). 8 warps, each owning
// 16 query rows (full key range -> softmax reductions are intra-quad shuffles).
// Loop over 8 key tiles: S = Q.K^T, online softmax, P overwrites K buffer,
// O += P.V^T. Attention matrix never touches DRAM.
// SMEM: Qs[128][132] | Ks/Ps[128][132] | Vs[128][132]  (202752 B dynamic)
// ---------------------------------------------------------------------------
#define FPAD 132
__global__ __launch_bounds__(256) void flash_k(
    const float* __restrict__ qkvt, const float* __restrict__ vt,
    float* __restrict__ aot)
{
    extern __shared__ float fs[];
    float* Qs = fs;                  // 128 x 132
    float* Ks = fs + 128 * FPAD;     // K tile, later P tile
    float* Vs = fs + 2 * 128 * FPAD;

    const int tid = threadIdx.x, w = tid >> 5, lane = tid & 31;
    const int lr = lane >> 2, lc = lane & 3;
    const int b = blockIdx.y >> 2, h = blockIdx.y & 3;
    const int n0 = blockIdx.x * 128;
    const float scale = 0.08838834764831845f;

    const float* Qg  = qkvt + (long)b * (3l * NC * NPIX) + (long)h * HD;
    const float* Kg  = Qg + NC;
    const float* Vtg = vt + (long)b * ((long)NC * NPIX) + (long)h * HD * NPIX;
    float*       Og  = aot + (long)b * ((long)NC * NPIX) + (long)h * HD;

    // prefetch K,V tile 0
    #pragma unroll
    for (int l = 0; l < 16; ++l) {
        int e = l * 256 + tid;
        int r = e >> 5, cq = (e & 31) << 2;
        CP_ASYNC16(smem_u32(Ks + r * FPAD + cq), Kg  + (long)r * 1536 + cq);
        CP_ASYNC16(smem_u32(Vs + r * FPAD + cq), Vtg + (long)r * 1024 + cq);
    }
    CP_COMMIT();

    // stage Q (scaled + tf32-rounded)
    #pragma unroll
    for (int l = 0; l < 16; ++l) {
        int e = l * 256 + tid;
        int r = e >> 5, cq = (e & 31) << 2;
        float4 v = *(const float4*)(Qg + (long)(n0 + r) * 1536 + cq);
        float* d = Qs + r * FPAD + cq;
        d[0] = rndf(v.x * scale); d[1] = rndf(v.y * scale);
        d[2] = rndf(v.z * scale); d[3] = rndf(v.w * scale);
    }

    float accO[16][4];
    #pragma unroll
    for (int j = 0; j < 16; ++j)
        #pragma unroll
        for (int q = 0; q < 4; ++q) accO[j][q] = 0.f;
    float m0s = -1e30f, m1s = -1e30f, l0s = 0.f, l1s = 0.f;

    const int qrow = w * 16 + lr;

    for (int t = 0; t < 8; ++t) {
        CP_WAIT0();
        __syncthreads();   // K,V (and Q on t=0) visible; prev P consumed

        // ---- S = Q . K^T ----
        float accS[16][4];
        #pragma unroll
        for (int j = 0; j < 16; ++j)
            #pragma unroll
            for (int q = 0; q < 4; ++q) accS[j][q] = 0.f;

        #pragma unroll
        for (int ks = 0; ks < 16; ++ks) {
            const float* Ar = Qs + qrow * FPAD + ks * 8 + lc;
            uint32_t a[4] = {
                __float_as_uint(Ar[0]),        __float_as_uint(Ar[8 * FPAD]),
                __float_as_uint(Ar[4]),        __float_as_uint(Ar[8 * FPAD + 4]) };
            #pragma unroll
            for (int j = 0; j < 16; ++j) {
                const float* Br = Ks + (j * 8 + lr) * FPAD + ks * 8 + lc;
                uint32_t bb[2] = { __float_as_uint(Br[0]), __float_as_uint(Br[4]) };
                mma1688(accS[j], a, bb);
            }
        }

        // ---- online softmax (rows lr and lr+8 of this warp's 16) ----
        float mx0 = -1e30f, mx1 = -1e30f;
        #pragma unroll
        for (int j = 0; j < 16; ++j) {
            mx0 = fmaxf(mx0, fmaxf(accS[j][0], accS[j][1]));
            mx1 = fmaxf(mx1, fmaxf(accS[j][2], accS[j][3]));
        }
        mx0 = fmaxf(mx0, __shfl_xor_sync(0xffffffffu, mx0, 1));
        mx0 = fmaxf(mx0, __shfl_xor_sync(0xffffffffu, mx0, 2));
        mx1 = fmaxf(mx1, __shfl_xor_sync(0xffffffffu, mx1, 1));
        mx1 = fmaxf(mx1, __shfl_xor_sync(0xffffffffu, mx1, 2));

        float mn0 = fmaxf(m0s, mx0), mn1 = fmaxf(m1s, mx1);
        float al0 = __expf(m0s - mn0), al1 = __expf(m1s - mn1);
        float s0 = 0.f, s1 = 0.f;
        #pragma unroll
        for (int j = 0; j < 16; ++j) {
            accS[j][0] = __expf(accS[j][0] - mn0);
            accS[j][1] = __expf(accS[j][1] - mn0);
            accS[j][2] = __expf(accS[j][2] - mn1);
            accS[j][3] = __expf(accS[j][3] - mn1);
            s0 += accS[j][0] + accS[j][1];
            s1 += accS[j][2] + accS[j][3];
        }
        s0 += __shfl_xor_sync(0xffffffffu, s0, 1);
        s0 += __shfl_xor_sync(0xffffffffu, s0, 2);
        s1 += __shfl_xor_sync(0xffffffffu, s1, 1);
        s1 += __shfl_xor_sync(0xffffffffu, s1, 2);
        l0s = l0s * al0 + s0;  l1s = l1s * al1 + s1;
        m0s = mn0;             m1s = mn1;
        #pragma unroll
        for (int j = 0; j < 16; ++j) {
            accO[j][0] *= al0; accO[j][1] *= al0;
            accO[j][2] *= al1; accO[j][3] *= al1;
        }

        __syncthreads();   // every warp done reading Ks before P overwrites it

        // ---- P -> SMEM (own rows only; intra-warp dependency) ----
        {
            float* P0 = Ks + qrow * FPAD;
            float* P1 = P0 + 8 * FPAD;
            #pragma unroll
            for (int j = 0; j < 16; ++j) {
                int cn = j * 8 + 2 * lc;
                P0[cn]     = rndf(accS[j][0]);
                P0[cn + 1] = rndf(accS[j][1]);
                P1[cn]     = rndf(accS[j][2]);
                P1[cn + 1] = rndf(accS[j][3]);
            }
        }
        __syncwarp();

        // ---- O += P . V^T ----
        #pragma unroll
        for (int ks = 0; ks < 16; ++ks) {
            const float* Ar = Ks + qrow * FPAD + ks * 8 + lc;
            uint32_t a[4] = {
                __float_as_uint(Ar[0]),        __float_as_uint(Ar[8 * FPAD]),
                __float_as_uint(Ar[4]),        __float_as_uint(Ar[8 * FPAD + 4]) };
            #pragma unroll
            for (int j = 0; j < 16; ++j) {
                const float* Br = Vs + (j * 8 + lr) * FPAD + ks * 8 + lc;
                uint32_t bb[2] = { __float_as_uint(Br[0]), __float_as_uint(Br[4]) };
                mma1688(accO[j], a, bb);
            }
        }

        __syncthreads();   // P/V consumption complete before reload

        if (t < 7) {
            long m0n = (long)(t + 1) * 128;
            #pragma unroll
            for (int l = 0; l < 16; ++l) {
                int e = l * 256 + tid;
                int r = e >> 5, cq = (e & 31) << 2;
                CP_ASYNC16(smem_u32(Ks + r * FPAD + cq),
                           Kg + (m0n + r) * 1536 + cq);
                CP_ASYNC16(smem_u32(Vs + r * FPAD + cq),
                           Vtg + (long)r * 1024 + m0n + cq);
            }
            CP_COMMIT();
        }
    }

    // ---- normalize + write (tf32-rounded: feeds proj GEMM) ----
    float i0 = 1.f / l0s, i1 = 1.f / l1s;
    int r0 = n0 + qrow;
    #pragma unroll
    for (int j = 0; j < 16; ++j) {
        int cn = j * 8 + 2 * lc;
        float2 v0 = make_float2(rndf(accO[j][0] * i0), rndf(accO[j][1] * i0));
        float2 v1 = make_float2(rndf(accO[j][2] * i1), rndf(accO[j][3] * i1));
        *(float2*)(Og + (long)r0 * NC + cn)       = v0;
        *(float2*)(Og + (long)(r0 + 8) * NC + cn) = v1;
    }
}

// ---------------------------------------------------------------------------
// kernel_launch
// Inputs: x, norm_w, norm_b, qkv_w, qkv_b, proj_w, proj_b
// ---------------------------------------------------------------------------
extern "C" void kernel_launch(void* const* d_in, const int* in_sizes, int n_in,
                              void* d_out, int out_size)
{
    const float* x      = (const float*)d_in[0];
    const float* norm_w = (const float*)d_in[1];
    const float* norm_b = (const float*)d_in[2];
    const float* qkv_w  = (const float*)d_in[3];
    const float* qkv_b  = (const float*)d_in[4];
    const float* proj_w = (const float*)d_in[5];
    const float* proj_b = (const float*)d_in[6];
    float* out = (float*)d_out;

    float *ht, *qkvt, *vt, *aot, *wq, *wp;
    cudaGetSymbolAddress((void**)&ht,   g_ht);
    cudaGetSymbolAddress((void**)&qkvt, g_qkvt);
    cudaGetSymbolAddress((void**)&vt,   g_vt);
    cudaGetSymbolAddress((void**)&aot,  g_aot);
    cudaGetSymbolAddress((void**)&wq,   g_wq);
    cudaGetSymbolAddress((void**)&wp,   g_wp);

    const long CN  = (long)NC * NPIX;            // 524288
    const long C3N = 3 * CN;                     // 1572864 (qkv_t per batch)

    const int FLASH_SMEM = 3 * 128 * FPAD * 4;   // 202752
    cudaFuncSetAttribute(flash_k,
                         cudaFuncAttributeMaxDynamicSharedMemorySize, FLASH_SMEM);

    // 0) Pre-round weights to tf32
    round_copy_k<<<(3 * NC * NC + 255) / 256, 256>>>(qkv_w, wq, 3 * NC * NC);
    round_copy_k<<<(NC * NC + 255) / 256, 256>>>(proj_w, wp, NC * NC);

    // 1) GroupNorm -> h_t[b][n][c] (tf32-rounded)
    groupnorm_t_k<<<NB * NGROUPS, 256>>>(x, norm_w, norm_b, ht);

    // 2) QKV: per batch  qkv_t[n, o] = h_t[n, :] . wq[o, :]  + bias[o]
    //    M=1024, N=1536, K=512  (output tf32-rounded: feeds flash)
    gemm_tc<true, false, false, false, true><<<dim3(12, 8, NB), 256>>>(
        ht, wq, qkv_b, nullptr, qkvt,
        /*K*/ 512, /*lda*/ 512, /*ldb*/ 512, /*ldc*/ 1536,
        /*a*/ CN, 0, /*b*/ 0, 0, /*c*/ C3N, 0, /*r*/ 0, 0,
        /*INNER*/ 1, 0.f);

    // 3) V transpose -> v_t[b][c2][m]
    transpose_v_k<<<dim3(32, 16, NB), 256>>>(qkvt, vt);

    // 4) Fused attention (scores + softmax + PV) -> ao_t[b][n][c]
    flash_k<<<dim3(NPIX / 128, NB * NHEADS), 256, FLASH_SMEM>>>(qkvt, vt, aot);

    // 5) Proj + bias + residual: out[co, n] = wp[co,:] . ao_t[n,:] + b[co] + x[co,n]
    //    M=512, N=1024, K=512
    gemm_tc<false, true, true, false, false><<<dim3(8, 4, NB), 256>>>(
        wp, aot, proj_b, x, out,
        /*K*/ 512, /*lda*/ 512, /*ldb*/ 512, /*ldc*/ 1024,
        /*a*/ 0, 0, /*b*/ CN, 0, /*c*/ CN, 0, /*r*/ CN, 0,
        /*INNER*/ 1, 0.f);
}